// round 17
// baseline (speedup 1.0000x reference)
#include <cuda_runtime.h>
#include <cuda_fp16.h>
#include <cstdint>

// Problem constants
#define B_  32
#define S_  256
#define D_  17
#define M_  512
#define H_  8
#define DK_ 64
#define NROW  139264          // B*S*D rows of width 512
#define NSAMP 8192            // B*S

// ---------------------------------------------------------------------------
// Scratch (__device__ globals; allocation-free rule)
// ---------------------------------------------------------------------------
__device__ __half g_q[(size_t)NROW * M_];
__device__ __half g_k[(size_t)NROW * M_];
__device__ __half g_v[(size_t)NROW * M_];
__device__ __half g_xh[(size_t)NROW * M_];      // x in fp16
__device__ __half g_ch[(size_t)NROW * M_];      // ctx in fp16
__device__ __half g_wh[4 * 512 * 512];          // Wq,Wk,Wv,Wo fp16 (contiguous)

// ---------------------------------------------------------------------------
// Helpers
// ---------------------------------------------------------------------------
__device__ __forceinline__ uint32_t smem_u32(const void* p) {
    uint32_t a;
    asm("{ .reg .u64 t; cvta.to.shared.u64 t, %1; cvt.u32.u64 %0, t; }"
        : "=r"(a) : "l"(p));
    return a;
}

__device__ __forceinline__ void cp16(uint32_t dst, const void* src) {
    asm volatile("cp.async.cg.shared.global [%0], [%1], 16;" :: "r"(dst), "l"(src));
}

__device__ __forceinline__ void ldmx4(uint32_t* r, uint32_t addr) {
    asm volatile("ldmatrix.sync.aligned.m8n8.x4.shared.b16 {%0,%1,%2,%3}, [%4];"
                 : "=r"(r[0]), "=r"(r[1]), "=r"(r[2]), "=r"(r[3]) : "r"(addr));
}

__device__ __forceinline__ void mma_f16(float* d, const uint32_t* a,
                                        uint32_t b0, uint32_t b1) {
    asm volatile(
        "mma.sync.aligned.m16n8k16.row.col.f32.f16.f16.f32 "
        "{%0,%1,%2,%3}, {%4,%5,%6,%7}, {%8,%9}, {%0,%1,%2,%3};"
        : "+f"(d[0]), "+f"(d[1]), "+f"(d[2]), "+f"(d[3])
        : "r"(a[0]), "r"(a[1]), "r"(a[2]), "r"(a[3]), "r"(b0), "r"(b1));
}

// ---------------------------------------------------------------------------
// Single-pass fp16 GEMM on HMMA, 256-thread / 16-warps-per-SM variant:
// C[r,c] = sum_k A[r,k] * W[c,k],  K=512, BK=64/iter, 8 iters, 2 stages.
// BM=BN=128, 256 threads (8 warps 4m x 2n), warp tile 32x64.
// launch_bounds(256,2): ~110 regs -> 2 CTAs/SM = 16 warps (4 per SMSP).
// MODE 0: fused q/k/v fp16 output. MODE 1: fp32 out + bias + resid.
// ---------------------------------------------------------------------------
#define ITERS 8
#define ROWB 144
#define STAGE_BYTES (256 * ROWB)
#define STAGES 2

__device__ __forceinline__ void load_iter(
    int tid, uint32_t sbase, int r0, int c0, int it,
    const __half* __restrict__ A, const __half* __restrict__ B)
{
    const int kk = it * 64;
    #pragma unroll
    for (int t = 0; t < 4; t++) {                 // A: 128 rows x 128B
        int f = tid + t * 256;
        int row = f >> 3, ch = f & 7;
        cp16(sbase + row * ROWB + ch * 16, A + ((size_t)(r0 + row) << 9) + kk + ch * 8);
    }
    const uint32_t b0 = sbase + 128 * ROWB;
    #pragma unroll
    for (int t = 0; t < 4; t++) {                 // B: 128 rows x 128B
        int f = tid + t * 256;
        int row = f >> 3, ch = f & 7;
        cp16(b0 + row * ROWB + ch * 16, B + ((size_t)(c0 + row) << 9) + kk + ch * 8);
    }
    asm volatile("cp.async.commit_group;");
}

template<int MODE>
__global__ __launch_bounds__(256, 2)
void gemm_f16(const __half* __restrict__ A, const __half* __restrict__ W,
              void* __restrict__ O0, void* __restrict__ O1, void* __restrict__ O2,
              const float* __restrict__ bias,
              const float* __restrict__ resid)
{
    extern __shared__ __align__(128) char smem[];

    const int tid = threadIdx.x;
    const int wid = tid >> 5;
    const int lid = tid & 31;
    const int c0 = blockIdx.x << 7;    // col tile (fast dim -> A L2 reuse)
    const int r0 = blockIdx.y << 7;
    const int m0 = (wid & 3) * 32;     // 4 warps in m
    const int n0 = (wid >> 2) * 64;    // 2 warps in n
    const uint32_t sb = smem_u32(smem);

    float acc[2][8][4];
    #pragma unroll
    for (int i = 0; i < 2; i++)
        #pragma unroll
        for (int j = 0; j < 8; j++)
            #pragma unroll
            for (int q = 0; q < 4; q++) acc[i][j][q] = 0.f;

    load_iter(tid, sb, r0, c0, 0, A, W);

    const uint32_t a_off = (uint32_t)((m0 + (lid & 15)) * ROWB + ((lid >> 4) << 4));
    const uint32_t b_off = (uint32_t)((n0 + (lid & 7) + ((lid >> 4) << 3)) * ROWB
                                      + (((lid >> 3) & 1) << 4));

    for (int it = 0; it < ITERS; it++) {
        asm volatile("cp.async.wait_group 0;");
        __syncthreads();

        if (it + 1 < ITERS)
            load_iter(tid, sb + ((it + 1) & 1) * STAGE_BYTES, r0, c0, it + 1, A, W);

        const uint32_t as = sb + (it & 1) * STAGE_BYTES;
        const uint32_t bs = as + 128 * ROWB;

        #pragma unroll
        for (int kt = 0; kt < 4; kt++) {
            uint32_t a[2][4], b[4][4];
            #pragma unroll
            for (int mi = 0; mi < 2; mi++)
                ldmx4(a[mi], as + a_off + (uint32_t)(mi * 16 * ROWB + kt * 32));
            #pragma unroll
            for (int nj = 0; nj < 4; nj++)
                ldmx4(b[nj], bs + b_off + (uint32_t)(nj * 16 * ROWB + kt * 32));
            #pragma unroll
            for (int mi = 0; mi < 2; mi++)
                #pragma unroll
                for (int ni = 0; ni < 8; ni++)
                    mma_f16(acc[mi][ni], a[mi],
                            b[ni >> 1][(ni & 1) * 2], b[ni >> 1][(ni & 1) * 2 + 1]);
        }
    }

    // Epilogue
    const int g  = lid >> 2;
    const int tg = lid & 3;
    if (MODE == 0) {
        const int which = c0 >> 9;
        __half* C = (__half*)((which == 0) ? O0 : (which == 1) ? O1 : O2);
        const int col0 = c0 & 511;
        #pragma unroll
        for (int mi = 0; mi < 2; mi++) {
            #pragma unroll
            for (int ni = 0; ni < 8; ni++) {
                const int r = r0 + m0 + mi * 16 + g;
                const int c = col0 + n0 + ni * 8 + tg * 2;
                *(__half2*)(C + ((size_t)r << 9) + c) =
                    __floats2half2_rn(acc[mi][ni][0], acc[mi][ni][1]);
                *(__half2*)(C + ((size_t)(r + 8) << 9) + c) =
                    __floats2half2_rn(acc[mi][ni][2], acc[mi][ni][3]);
            }
        }
    } else {
        float* C = (float*)O0;
        #pragma unroll
        for (int mi = 0; mi < 2; mi++) {
            #pragma unroll
            for (int ni = 0; ni < 8; ni++) {
                const int r = r0 + m0 + mi * 16 + g;
                const int c = c0 + n0 + ni * 8 + tg * 2;
                float2 v0 = make_float2(acc[mi][ni][0], acc[mi][ni][1]);
                float2 v1 = make_float2(acc[mi][ni][2], acc[mi][ni][3]);
                const float2 bb = *(const float2*)(bias + c);
                const float2 q0 = *(const float2*)(resid + ((size_t)r << 9) + c);
                const float2 q1 = *(const float2*)(resid + ((size_t)(r + 8) << 9) + c);
                v0.x += bb.x + q0.x; v0.y += bb.y + q0.y;
                v1.x += bb.x + q1.x; v1.y += bb.y + q1.y;
                *(float2*)(C + ((size_t)r << 9) + c)       = v0;
                *(float2*)(C + ((size_t)(r + 8) << 9) + c) = v1;
            }
        }
    }
}

// ---------------------------------------------------------------------------
// Merged convert: x (NX4 float4s) then Wq/Wk/Wv/Wo (65536 float4s each)
// ---------------------------------------------------------------------------
#define NX4 17825792
__global__ __launch_bounds__(256)
void convert_all(const float* __restrict__ x,
                 const float* __restrict__ Wq, const float* __restrict__ Wk,
                 const float* __restrict__ Wv, const float* __restrict__ Wo,
                 __half* __restrict__ xh, __half* __restrict__ wh)
{
    const int i = blockIdx.x * 256 + threadIdx.x;
    const float* src;
    __half2* dst;
    int idx;
    if (i < NX4) {
        src = x; idx = i; dst = (__half2*)xh;
    } else {
        int j = i - NX4;
        int w = j >> 16, jj = j & 65535;
        src = (w == 0) ? Wq : (w == 1) ? Wk : (w == 2) ? Wv : Wo;
        idx = jj;
        dst = (__half2*)(wh + (size_t)w * 262144);
    }
    float4 v = ((const float4*)src)[idx];
    dst[2 * idx]     = __floats2half2_rn(v.x, v.y);
    dst[2 * idx + 1] = __floats2half2_rn(v.z, v.w);
}

// ---------------------------------------------------------------------------
// Attention v7 (R15/R16, unchanged): fp16 q/k/v staging, fp32 scores.
// BUF0h = q then v, BUF1h = k (half stride 72). Padded score writes.
// ---------------------------------------------------------------------------
#define AB0H 0
#define AB1H 4896                // halves (4 heads * 17 rows * 72)
#define ASSF 4896                // floats: scores 4*400
#define ASPF 6496                // floats: P 400
__global__ __launch_bounds__(128)
void attn_kernel(const __half* __restrict__ q, const __half* __restrict__ k,
                 const __half* __restrict__ v, const float* __restrict__ P,
                 __half* __restrict__ ch)
{
    __shared__ float sm[6896];   // 27584 bytes
    __half* smh = (__half*)sm;
    const int n  = blockIdx.x;
    const int hg = blockIdx.y;
    const int t  = threadIdx.x;
    const size_t base = (size_t)n * D_ * M_;
    const uint32_t smb = smem_u32(sm);

    // Phase 1: cp.async stage q -> BUF0h, k -> BUF1h
    #pragma unroll
    for (int u = 0; u < 5; u++) {
        int f = t + u * 128;
        if (f < 544) {
            int row = f >> 3, c8 = f & 7;        // row = h*17+d (0..67)
            int h = row / 17, d = row % 17;
            size_t goff = base + (size_t)d * 512 + (hg * 4 + h) * 64 + c8 * 8;
            uint32_t soff = (uint32_t)((row * 72 + c8 * 8) * 2);
            cp16(smb + AB0H * 2 + soff, q + goff);
            cp16(smb + AB1H * 2 + soff, k + goff);
        }
    }
    asm volatile("cp.async.commit_group;");
    for (int f = t; f < 289; f += 128)
        sm[ASPF + (f / 17) * 20 + (f % 17)] = P[f];
    asm volatile("cp.async.wait_group 0;");
    __syncthreads();

    // Phase 2: scores (padded 4x4 blocks), fp16 loads -> fp32 math
    if (t < 100) {
        const int h = t / 25, blk = t % 25;
        const int d0 = (blk / 5) * 4, e0 = (blk % 5) * 4;
        const __half* sq = smh + AB0H + (h * 17 + d0) * 72;
        const __half* sk = smh + AB1H + (h * 17 + e0) * 72;
        float acc[4][4];
        #pragma unroll
        for (int i = 0; i < 4; i++)
            #pragma unroll
            for (int j = 0; j < 4; j++) acc[i][j] = 0.f;
        #pragma unroll 8
        for (int c4 = 0; c4 < 16; c4++) {
            float4 qa[4], kb[4];
            #pragma unroll
            for (int i = 0; i < 4; i++) {
                uint2 u = *(const uint2*)(sq + i * 72 + c4 * 4);
                float2 f0 = __half22float2(*(__half2*)&u.x);
                float2 f1 = __half22float2(*(__half2*)&u.y);
                qa[i] = make_float4(f0.x, f0.y, f1.x, f1.y);
            }
            #pragma unroll
            for (int j = 0; j < 4; j++) {
                uint2 u = *(const uint2*)(sk + j * 72 + c4 * 4);
                float2 f0 = __half22float2(*(__half2*)&u.x);
                float2 f1 = __half22float2(*(__half2*)&u.y);
                kb[j] = make_float4(f0.x, f0.y, f1.x, f1.y);
            }
            #pragma unroll
            for (int i = 0; i < 4; i++)
                #pragma unroll
                for (int j = 0; j < 4; j++)
                    acc[i][j] += qa[i].x * kb[j].x + qa[i].y * kb[j].y
                               + qa[i].z * kb[j].z + qa[i].w * kb[j].w;
        }
        float* ss = sm + ASSF + h * 400;
        #pragma unroll
        for (int i = 0; i < 4; i++)
            #pragma unroll
            for (int j = 0; j < 4; j++)
                ss[(d0 + i) * 20 + e0 + j] =
                    acc[i][j] * 0.125f + sm[ASPF + (d0 + i) * 20 + e0 + j];
    }
    __syncthreads();

    // Phase 3: cp.async v into BUF0h (q dead); softmax overlaps.
    #pragma unroll
    for (int u = 0; u < 5; u++) {
        int f = t + u * 128;
        if (f < 544) {
            int row = f >> 3, c8 = f & 7;
            int h = row / 17, d = row % 17;
            size_t goff = base + (size_t)d * 512 + (hg * 4 + h) * 64 + c8 * 8;
            uint32_t soff = (uint32_t)((row * 72 + c8 * 8) * 2);
            cp16(smb + AB0H * 2 + soff, v + goff);
        }
    }
    asm volatile("cp.async.commit_group;");
    if (t < 68) {
        float* row = sm + ASSF + (t / 17) * 400 + (t % 17) * 20;
        float mx = -1e30f;
        #pragma unroll
        for (int e = 0; e < 17; e++) mx = fmaxf(mx, row[e]);
        float sum = 0.f;
        #pragma unroll
        for (int e = 0; e < 17; e++) {
            float ex = __expf(row[e] - mx);
            row[e] = ex;
            sum += ex;
        }
        float inv = 1.f / sum;
        #pragma unroll
        for (int e = 0; e < 17; e++) row[e] *= inv;
    }
    asm volatile("cp.async.wait_group 0;");
    __syncthreads();

    // Phase 4: ctx -> row-major fp16 (contiguous 8B stores)
    for (int task = t; task < 320; task += 128) {
        const int h = task / 80, rem = task % 80;
        const int d0 = (rem / 16) * 4, c0c = (rem % 16) * 4;
        const float* ss = sm + ASSF + h * 400;
        const __half* sv = smh + AB0H + h * 17 * 72 + c0c;
        float acc[4][4];
        #pragma unroll
        for (int i = 0; i < 4; i++)
            #pragma unroll
            for (int j = 0; j < 4; j++) acc[i][j] = 0.f;
        #pragma unroll
        for (int e = 0; e < 17; e++) {
            uint2 u = *(const uint2*)(sv + e * 72);
            float2 f0 = __half22float2(*(__half2*)&u.x);
            float2 f1 = __half22float2(*(__half2*)&u.y);
            #pragma unroll
            for (int i = 0; i < 4; i++) {
                const float w = ss[(d0 + i) * 20 + e];
                acc[i][0] += w * f0.x;
                acc[i][1] += w * f0.y;
                acc[i][2] += w * f1.x;
                acc[i][3] += w * f1.y;
            }
        }
        #pragma unroll
        for (int i = 0; i < 4; i++) {
            const int d = d0 + i;
            if (d < 17) {
                const size_t off = base + (size_t)d * 512 + (hg * 4 + h) * 64 + c0c;
                __half2 h0 = __floats2half2_rn(acc[i][0], acc[i][1]);
                __half2 h1 = __floats2half2_rn(acc[i][2], acc[i][3]);
                uint2 o;
                o.x = *(uint32_t*)&h0;
                o.y = *(uint32_t*)&h1;
                *(uint2*)(ch + off) = o;
            }
        }
    }
}

// ---------------------------------------------------------------------------
// In-place LayerNorm (warp per row, width 512), eps = 1e-5
// ---------------------------------------------------------------------------
__global__ __launch_bounds__(256)
void ln_kernel(float* __restrict__ out, const float* __restrict__ gamma,
               const float* __restrict__ beta)
{
    const int row  = blockIdx.x * 8 + (threadIdx.x >> 5);
    const int lane = threadIdx.x & 31;
    const size_t base = (size_t)row * 512;

    float4 vals[4];
    float sum = 0.f, sq = 0.f;
    #pragma unroll
    for (int j = 0; j < 4; j++) {
        vals[j] = *(const float4*)(out + base + (size_t)(j * 32 + lane) * 4);
        sum += vals[j].x + vals[j].y + vals[j].z + vals[j].w;
        sq  += vals[j].x * vals[j].x + vals[j].y * vals[j].y
             + vals[j].z * vals[j].z + vals[j].w * vals[j].w;
    }
    #pragma unroll
    for (int o = 16; o > 0; o >>= 1) {
        sum += __shfl_xor_sync(0xffffffffu, sum, o);
        sq  += __shfl_xor_sync(0xffffffffu, sq,  o);
    }
    const float mean = sum * (1.f / 512.f);
    const float var  = sq * (1.f / 512.f) - mean * mean;
    const float rstd = rsqrtf(var + 1e-5f);

    #pragma unroll
    for (int j = 0; j < 4; j++) {
        int c = (j * 32 + lane) * 4;
        float4 g  = *(const float4*)(gamma + c);
        float4 bb = *(const float4*)(beta + c);
        float4 v;
        v.x = (vals[j].x - mean) * rstd * g.x + bb.x;
        v.y = (vals[j].y - mean) * rstd * g.y + bb.y;
        v.z = (vals[j].z - mean) * rstd * g.z + bb.z;
        v.w = (vals[j].w - mean) * rstd * g.w + bb.w;
        *(float4*)(out + base + c) = v;
    }
}

// ---------------------------------------------------------------------------
extern "C" void kernel_launch(void* const* d_in, const int* in_sizes, int n_in,
                              void* d_out, int out_size)
{
    const float* x     = (const float*)d_in[0];
    const float* P     = (const float*)d_in[1];
    const float* Wq    = (const float*)d_in[2];
    const float* Wk    = (const float*)d_in[3];
    const float* Wv    = (const float*)d_in[4];
    const float* Wo    = (const float*)d_in[5];
    const float* bo    = (const float*)d_in[6];
    const float* gamma = (const float*)d_in[7];
    const float* beta  = (const float*)d_in[8];
    float* out = (float*)d_out;

    void *pq, *pk, *pv, *pxh, *pch, *pwh;
    cudaGetSymbolAddress(&pq,  g_q);
    cudaGetSymbolAddress(&pk,  g_k);
    cudaGetSymbolAddress(&pv,  g_v);
    cudaGetSymbolAddress(&pxh, g_xh);
    cudaGetSymbolAddress(&pch, g_ch);
    cudaGetSymbolAddress(&pwh, g_wh);

    __half* wh = (__half*)pwh;

    const int dsm = STAGES * STAGE_BYTES;           // 73728
    cudaFuncSetAttribute(gemm_f16<0>, cudaFuncAttributeMaxDynamicSharedMemorySize, dsm);
    cudaFuncSetAttribute(gemm_f16<1>, cudaFuncAttributeMaxDynamicSharedMemorySize, dsm);

    // Merged convert: 18087936 float4s = 70656 blocks
    convert_all<<<70656, 256>>>(x, Wq, Wk, Wv, Wo, (__half*)pxh, wh);

    // Fused QKV projection: 12 col tiles over contiguous [Wq;Wk;Wv] rows
    dim3 gq(12, NROW / 128);
    gemm_f16<0><<<gq, 256, dsm>>>((const __half*)pxh, wh,
                                  pq, pk, pv, nullptr, nullptr);

    dim3 ga(NSAMP, 2);
    attn_kernel<<<ga, 128>>>(
        (const __half*)pq, (const __half*)pk, (const __half*)pv, P, (__half*)pch);

    // fc_out + bias + residual
    dim3 go(4, NROW / 128);
    gemm_f16<1><<<go, 256, dsm>>>((const __half*)pch, wh + 3 * 262144,
                                  out, nullptr, nullptr, bo, x);

    ln_kernel<<<NROW / 8, 256>>>(out, gamma, beta);
}